// round 10
// baseline (speedup 1.0000x reference)
#include <cuda_runtime.h>
#include <cstdint>

#define BATCH 16
#define NN 1408
#define DIM 256
#define HD 64
#define BN (BATCH*NN)
#define KSEL 211
#define NT 22
#define NPB (NT*NT*BATCH*4)
#define SZ ((size_t)BATCH*NN*NN)

typedef unsigned long long u64;

__device__ __align__(16) float g_z[(size_t)BN*DIM];
__device__ __align__(16) float g_h1[(size_t)BN*128];
__device__ __align__(16) float g_sq[4*BN];
__device__ __align__(16) float g_dist4[4*SZ];
__device__ __align__(16) float g_thr4[4*BN];
__device__ __align__(16) int   g_tie4[4*BN];
__device__ __align__(16) float g_score[BN];
__device__ __align__(16) float g_w[3*BN];
__device__ __align__(16) float g_projT[DIM*DIM];
__device__ __align__(16) float g_w1T[DIM*128];
__device__ __align__(16) float g_partial[NPB];
__device__ float g_inv4[4];

__device__ __forceinline__ u64 pack2(float lo, float hi){
    u64 r; asm("mov.b64 %0, {%1, %2};" : "=l"(r) : "f"(lo), "f"(hi)); return r;
}
__device__ __forceinline__ u64 fma2(u64 a, u64 b, u64 c){
    u64 d; asm("fma.rn.f32x2 %0, %1, %2, %3;" : "=l"(d) : "l"(a), "l"(b), "l"(c)); return d;
}
__device__ __forceinline__ float2 unpack2(u64 v){
    float2 f; asm("mov.b64 {%0, %1}, %2;" : "=f"(f.x), "=f"(f.y) : "l"(v)); return f;
}

__global__ void prep_kernel(const float* __restrict__ proj_w,
                            const float* __restrict__ score_w1) {
    int idx = blockIdx.x * 256 + threadIdx.x;
    int c = idx >> 8, k = idx & 255;
    g_projT[k * DIM + c] = proj_w[idx];
    if (idx < 128 * 256) g_w1T[k * 128 + c] = score_w1[idx];
}

template<int NOUT, bool IS_Z>
__global__ void __launch_bounds__(256, 4) gemm_kernel(const float* __restrict__ A,
                                                      const float* __restrict__ bias) {
    const float* Bt = IS_Z ? g_projT : g_w1T;
    float*       C  = IS_Z ? g_z     : g_h1;
    __shared__ __align__(16) float As[32][68];
    __shared__ __align__(16) float Bs[32][68];
    const int t = threadIdx.x, tx = t & 15, ty = t >> 4;
    const int m0 = blockIdx.y * 64, n0 = blockIdx.x * 64;
    u64 acc[4][2] = {};
    for (int k0 = 0; k0 < DIM; k0 += 32) {
        #pragma unroll
        for (int i = 0; i < 8; i++) {
            int e = t + i * 256, r = e >> 5, k = e & 31;
            As[k][r] = A[(size_t)(m0 + r) * DIM + k0 + k];
        }
        #pragma unroll
        for (int i = 0; i < 8; i++) {
            int e = t + i * 256, c = e & 63, k = e >> 6;
            Bs[k][c] = Bt[(size_t)(k0 + k) * NOUT + n0 + c];
        }
        __syncthreads();
        #pragma unroll 8
        for (int k = 0; k < 32; k++) {
            float4 bf = *reinterpret_cast<const float4*>(&Bs[k][tx*4]);
            float4 af = *reinterpret_cast<const float4*>(&As[k][ty*4]);
            u64 b01 = pack2(bf.x, bf.y), b23 = pack2(bf.z, bf.w);
            const float av[4] = {af.x, af.y, af.z, af.w};
            #pragma unroll
            for (int i = 0; i < 4; i++) {
                u64 aa = pack2(av[i], av[i]);
                acc[i][0] = fma2(aa, b01, acc[i][0]);
                acc[i][1] = fma2(aa, b23, acc[i][1]);
            }
        }
        __syncthreads();
    }
    #pragma unroll
    for (int i = 0; i < 4; i++) {
        float2 v01 = unpack2(acc[i][0]), v23 = unpack2(acc[i][1]);
        float v[4] = {v01.x, v01.y, v23.x, v23.y};
        float4 o;
        #pragma unroll
        for (int j = 0; j < 4; j++) {
            float val = v[j];
            if (!IS_Z) {
                val += bias[n0 + tx*4 + j];
                val = 0.5f * val * (1.0f + erff(val * 0.70710678118654752f));
            }
            ((float*)&o)[j] = val;
        }
        *reinterpret_cast<float4*>(&C[(size_t)(m0 + ty*4 + i) * NOUT + n0 + tx*4]) = o;
        if (IS_Z) {
            float sq = v[0]*v[0] + v[1]*v[1] + v[2]*v[2] + v[3]*v[3];
            #pragma unroll
            for (int off = 8; off; off >>= 1)
                sq += __shfl_down_sync(0xffffffffu, sq, off, 16);
            if (tx == 0) g_sq[blockIdx.x * BN + m0 + ty*4 + i] = sq;
        }
    }
}

__global__ void score_kernel(const float* __restrict__ w2, const float* __restrict__ b2) {
    const int n = blockIdx.x, t = threadIdx.x;
    float s = g_h1[(size_t)n * 128 + t] * w2[t];
    #pragma unroll
    for (int off = 16; off; off >>= 1) s += __shfl_down_sync(0xffffffffu, s, off);
    __shared__ float sw[4];
    if ((t & 31) == 0) sw[t >> 5] = s;
    __syncthreads();
    if (t == 0) {
        float v = sw[0] + sw[1] + sw[2] + sw[3] + b2[0];
        g_score[n] = 1.0f / (1.0f + expf(-v));
    }
}

__global__ void gate_kernel(const float* __restrict__ x, const float* __restrict__ gw,
                            const float* __restrict__ gb) {
    const int lane = threadIdx.x & 31;
    const int n = blockIdx.x * 8 + (threadIdx.x >> 5);
    const float* xr = x + (size_t)n * DIM;
    float a0 = 0.f, a1 = 0.f, a2 = 0.f;
    for (int k = lane; k < DIM; k += 32) {
        float xv = xr[k];
        a0 += xv * gw[k]; a1 += xv * gw[DIM + k]; a2 += xv * gw[2*DIM + k];
    }
    #pragma unroll
    for (int off = 16; off; off >>= 1) {
        a0 += __shfl_down_sync(0xffffffffu, a0, off);
        a1 += __shfl_down_sync(0xffffffffu, a1, off);
        a2 += __shfl_down_sync(0xffffffffu, a2, off);
    }
    if (lane == 0) {
        float p0 = a0 + gb[0], p1 = a1 + gb[1], p2 = a2 + gb[2];
        float mx = fmaxf(p0, fmaxf(p1, p2));
        float e0 = expf(p0 - mx), e1 = expf(p1 - mx), e2 = expf(p2 - mx);
        float es = e0 + e1 + e2;
        float pr[3] = {e0/es, e1/es, e2/es};
        int pos[3];
        #pragma unroll
        for (int a = 0; a < 3; a++) {
            int c = 0;
            #pragma unroll
            for (int b = 0; b < 3; b++)
                c += ((pr[b] > pr[a]) || (pr[b] == pr[a] && b < a)) ? 1 : 0;
            pos[a] = c;
        }
        float sp[3];
        #pragma unroll
        for (int a = 0; a < 3; a++) sp[pos[a]] = pr[a];
        float c1 = sp[0] + sp[1];
        float c2 = c1 + sp[2];
        if (!((c1 - sp[1]) < 0.85f)) sp[1] = 0.f;
        if (!((c2 - sp[2]) < 0.85f)) sp[2] = 0.f;
        float w0 = sp[pos[0]], w1 = sp[pos[1]], w2v = sp[pos[2]];
        float scale = 1.0f / (w0 + w1 + w2v + 1e-8f);
        g_w[n]        = w0  * scale;
        g_w[BN + n]   = w1  * scale;
        g_w[2*BN + n] = w2v * scale;
    }
}

__global__ void __launch_bounds__(256, 4) gram_kernel() {
    const int tj = blockIdx.x, ti = blockIdx.y;
    const int z = blockIdx.z, h = z >> 4, b = z & 15;
    const int pidx = z * (NT*NT) + ti*NT + tj;
    if (tj < ti) { if (threadIdx.x == 0) g_partial[pidx] = 0.f; return; }
    __shared__ __align__(16) float Az[64][68];
    __shared__ __align__(16) float Bz[64][68];
    __shared__ float sred[8];
    const int t = threadIdx.x, tx = t & 15, ty = t >> 4;
    const int i0 = ti*64, j0 = tj*64;
    const float* zb = g_z + (size_t)b * NN * DIM + h * HD;
    #pragma unroll
    for (int i = 0; i < 16; i++) {
        int e = t + i * 256, k = e & 63, r = e >> 6;
        Az[k][r] = zb[(size_t)(i0 + r) * DIM + k];
        Bz[k][r] = zb[(size_t)(j0 + r) * DIM + k];
    }
    __syncthreads();
    u64 acc[4][2] = {};
    #pragma unroll 16
    for (int k = 0; k < 64; k++) {
        float4 bf = *reinterpret_cast<const float4*>(&Bz[k][tx*4]);
        float4 af = *reinterpret_cast<const float4*>(&Az[k][ty*4]);
        u64 b01 = pack2(bf.x, bf.y), b23 = pack2(bf.z, bf.w);
        const float av[4] = {af.x, af.y, af.z, af.w};
        #pragma unroll
        for (int i = 0; i < 4; i++) {
            u64 aa = pack2(av[i], av[i]);
            acc[i][0] = fma2(aa, b01, acc[i][0]);
            acc[i][1] = fma2(aa, b23, acc[i][1]);
        }
    }
    const float* sqb = g_sq + h * BN + b * NN;
    float* dbase = g_dist4 + (size_t)h * SZ + (size_t)b * NN * NN;
    float lsum = 0.f;
    float dval[4][4];
    #pragma unroll
    for (int i = 0; i < 4; i++) {
        float sqi = sqb[i0 + ty*4 + i];
        float2 v01 = unpack2(acc[i][0]), v23 = unpack2(acc[i][1]);
        float dot[4] = {v01.x, v01.y, v23.x, v23.y};
        #pragma unroll
        for (int j = 0; j < 4; j++) {
            float d2 = sqi + sqb[j0 + tx*4 + j] - 2.0f * dot[j];
            float dv = (d2 > 0.f) ? sqrtf(d2) : 0.f;
            dval[i][j] = dv;
            lsum += dv;
        }
        *reinterpret_cast<float4*>(&dbase[(size_t)(i0 + ty*4 + i) * NN + j0 + tx*4]) =
            make_float4(dval[i][0], dval[i][1], dval[i][2], dval[i][3]);
    }
    #pragma unroll
    for (int off = 16; off; off >>= 1) lsum += __shfl_down_sync(0xffffffffu, lsum, off);
    if ((t & 31) == 0) sred[t >> 5] = lsum;
    if (tj > ti) {
        __syncthreads();
        #pragma unroll
        for (int i = 0; i < 4; i++)
            #pragma unroll
            for (int j = 0; j < 4; j++)
                Az[tx*4 + j][ty*4 + i] = dval[i][j];
        __syncthreads();
        #pragma unroll
        for (int it = 0; it < 16; it++) {
            int e = t + it * 256, c = e & 63, r = e >> 6;
            dbase[(size_t)(j0 + r) * NN + i0 + c] = Az[r][c];
        }
    } else {
        __syncthreads();
    }
    if (t == 0) {
        float s = 0.f;
        #pragma unroll
        for (int wv = 0; wv < 8; wv++) s += sred[wv];
        g_partial[pidx] = (tj > ti) ? 2.0f * s : s;
    }
}

__global__ void reduce_kernel() {
    const int h = blockIdx.x;
    __shared__ float s[256];
    float a = 0.f;
    for (int i = threadIdx.x; i < NT*NT*BATCH; i += 256)
        a += g_partial[h * (NT*NT*BATCH) + i];
    s[threadIdx.x] = a;
    __syncthreads();
    for (int off = 128; off; off >>= 1) {
        if (threadIdx.x < off) s[threadIdx.x] += s[threadIdx.x + off];
        __syncthreads();
    }
    if (threadIdx.x == 0) {
        float mean = s[0] / 31719424.0f;
        g_inv4[h] = 1.0f / (2.0f * mean * mean + 1e-8f);
    }
}

// warp-per-row radix select: no block syncs, no atomics, match-dedup hist,
// ballot+__fns tie find. Block = 4 warps = 4 rows.
__global__ void __launch_bounds__(128, 8) select_kernel() {
    __shared__ unsigned rowv[4][45*32];    // slot (lane*45+i) holds value at j=i*32+lane
    __shared__ unsigned hist[4][256];
    const int t = threadIdx.x, wrp = t >> 5, lane = t & 31;
    const unsigned FULL = 0xffffffffu;
    const int row = blockIdx.x * 4 + wrp;
    const int h = 3 - blockIdx.y;          // head 3 first: last written -> L2 hits
    const uint4* dp4 = (const uint4*)(g_dist4 + (size_t)h * SZ + (size_t)row * NN);
    unsigned* rv = rowv[wrp];
    unsigned* hs = hist[wrp];
    #pragma unroll
    for (int i = 0; i < 11; i++) {
        int j4 = i * 32 + lane;            // 352 uint4 per row
        uint4 v = dp4[j4];
        int e0 = 4 * j4;
        rv[((e0    ) & 31) * 45 + ((e0    ) >> 5)] = v.x;
        rv[((e0 + 1) & 31) * 45 + ((e0 + 1) >> 5)] = v.y;
        rv[((e0 + 2) & 31) * 45 + ((e0 + 2) >> 5)] = v.z;
        rv[((e0 + 3) & 31) * 45 + ((e0 + 3) >> 5)] = v.w;
    }
    __syncwarp();
    unsigned prefix = 0; int rem = KSEL, ceq = 0;
    #pragma unroll
    for (int pass = 0; pass < 4; pass++) {
        const int shift = 24 - 8 * pass;
        const unsigned himask = pass ? (0xFFFFFFFFu << (shift + 8)) : 0u;
        #pragma unroll
        for (int i = 0; i < 8; i++) hs[lane * 8 + i] = 0;
        __syncwarp();
        for (int i = 0; i < 44; i++) {
            unsigned u = rv[lane * 45 + i];
            bool act = (u & himask) == prefix;
            unsigned bin = (u >> shift) & 255u;
            unsigned key = act ? bin : (0x100u + lane);
            unsigned mm = __match_any_sync(FULL, key);
            if (act && lane == (int)(__ffs(mm) - 1))
                hs[bin] += (unsigned)__popc(mm);
        }
        __syncwarp();
        unsigned seg = 0;
        #pragma unroll
        for (int i = 0; i < 8; i++) seg += hs[lane * 8 + i];
        unsigned incl = seg;
        #pragma unroll
        for (int o = 1; o < 32; o <<= 1) {
            unsigned nb = __shfl_up_sync(FULL, incl, o);
            if (lane >= o) incl += nb;
        }
        unsigned excl = incl - seg;
        unsigned vote = __ballot_sync(FULL, excl < (unsigned)rem && (unsigned)rem <= incl);
        int src = (int)(__ffs(vote) - 1);
        unsigned binf = 0, nrem = 0, ncq = 0;
        if (lane == src) {
            unsigned c = excl;
            #pragma unroll
            for (int i = 0; i < 8; i++) {
                unsigned hc = hs[lane * 8 + i];
                if (c + hc >= (unsigned)rem) { binf = lane * 8 + i; nrem = rem - c; ncq = hc; break; }
                c += hc;
            }
        }
        binf = __shfl_sync(FULL, binf, src);
        nrem = __shfl_sync(FULL, nrem, src);
        ncq  = __shfl_sync(FULL, ncq,  src);
        prefix |= binf << shift;
        rem = (int)nrem; ceq = (int)ncq;
        __syncwarp();
    }
    int tieIdx = 0x7fffffff;
    if (rem < ceq) {
        int cum = 0; bool done = false;
        for (int i = 0; i < 44 && !done; i++) {
            unsigned u = rv[lane * 45 + i];
            unsigned bal = __ballot_sync(FULL, u == prefix);
            int n = __popc(bal);
            if (cum + n >= rem) {
                tieIdx = i * 32 + (int)__fns(bal, 0, rem - cum);
                done = true;
            }
            cum += n;
        }
    }
    if (lane == 0) {
        g_thr4[h * BN + row] = __uint_as_float(prefix);
        g_tie4[h * BN + row] = tieIdx;
    }
}

__global__ void combine_kernel(float* __restrict__ out,
                               const float* __restrict__ tmask,
                               const float* __restrict__ smask,
                               const float* __restrict__ thrp) {
    const int i = blockIdx.x, b = blockIdx.y;
    const int row = b * NN + i;
    const int j0 = threadIdx.x * 4;
    const size_t roff = (size_t)b * NN * NN + (size_t)i * NN + j0;
    float adj[4] = {0.f, 0.f, 0.f, 0.f};
    #pragma unroll
    for (int h = 0; h < 4; h++) {
        const float inv  = g_inv4[h];
        const float thri = g_thr4[h*BN + row];
        const int   tiei = g_tie4[h*BN + row];
        const float4 d4  = *reinterpret_cast<const float4*>(&g_dist4[(size_t)h * SZ + roff]);
        const float4 tj4 = *reinterpret_cast<const float4*>(&g_thr4[h*BN + b*NN + j0]);
        const int4   te4 = *reinterpret_cast<const int4*>(&g_tie4[h*BN + b*NN + j0]);
        const float dv[4]  = {d4.x, d4.y, d4.z, d4.w};
        const float tjv[4] = {tj4.x, tj4.y, tj4.z, tj4.w};
        const int   tev[4] = {te4.x, te4.y, te4.z, te4.w};
        #pragma unroll
        for (int l = 0; l < 4; l++) {
            int j = j0 + l;
            float d = dv[l];
            bool m = (d < thri) || (d == thri && j <= tiei) ||
                     (d < tjv[l]) || (d == tjv[l] && i <= tev[l]);
            if (m) adj[l] += __expf(-d * d * inv);
        }
    }
    const float T   = thrp[0];
    const float si  = g_score[row];
    const float wti = g_w[row], wsi = g_w[BN + row], wpi = g_w[2*BN + row];
    const float4 sj  = *reinterpret_cast<const float4*>(&g_score[b*NN + j0]);
    const float4 wtj = *reinterpret_cast<const float4*>(&g_w[b*NN + j0]);
    const float4 wsj = *reinterpret_cast<const float4*>(&g_w[BN + b*NN + j0]);
    const float4 wpj = *reinterpret_cast<const float4*>(&g_w[2*BN + b*NN + j0]);
    const float4 tm4 = *reinterpret_cast<const float4*>(&tmask[(size_t)i * NN + j0]);
    const float4 sm4 = *reinterpret_cast<const float4*>(&smask[(size_t)i * NN + j0]);
    const float sjv[4]  = {sj.x, sj.y, sj.z, sj.w};
    const float wtjv[4] = {wtj.x, wtj.y, wtj.z, wtj.w};
    const float wsjv[4] = {wsj.x, wsj.y, wsj.z, wsj.w};
    const float wpjv[4] = {wpj.x, wpj.y, wpj.z, wpj.w};
    const float tmv[4]  = {tm4.x, tm4.y, tm4.z, tm4.w};
    const float smv[4]  = {sm4.x, sm4.y, sm4.z, sm4.w};
    float4 res;
    #pragma unroll
    for (int l = 0; l < 4; l++) {
        float a = adj[l] * 0.25f;
        float gate_t = tmv[l] * 0.5f * (wti + wtjv[l]);
        float gate_s = smv[l] * 0.5f * (wsi + wsjv[l]);
        float ew  = si * sjv[l];
        // sigmoid(10(ew-T)) = 1/(1+2^(K(T-ew))), reciprocal via Newton (no RCP MUFU)
        float e2  = exp2f(14.4269504088896341f * (T - ew));
        float den = 1.0f + e2;
        float r = __uint_as_float(0x7EF311C3u - __float_as_uint(den));
        r = r * (2.0f - den * r);
        r = r * (2.0f - den * r);
        r = r * (2.0f - den * r);
        float gate_p = r * 0.5f * (wpi + wpjv[l]);
        ((float*)&res)[l] = a * (gate_t + gate_s + gate_p);
    }
    *reinterpret_cast<float4*>(&out[roff]) = res;
}

extern "C" void kernel_launch(void* const* d_in, const int* in_sizes, int n_in,
                              void* d_out, int out_size) {
    const float* x        = (const float*)d_in[0];
    const float* proj_w   = (const float*)d_in[1];
    const float* gate_w   = (const float*)d_in[2];
    const float* gate_b   = (const float*)d_in[3];
    const float* score_w1 = (const float*)d_in[4];
    const float* score_b1 = (const float*)d_in[5];
    const float* score_w2 = (const float*)d_in[6];
    const float* score_b2 = (const float*)d_in[7];
    const float* thr      = (const float*)d_in[8];
    const float* tmask    = (const float*)d_in[9];
    const float* smask    = (const float*)d_in[10];
    float* out = (float*)d_out;

    // capture slot #3 = new warp-per-row select
    prep_kernel<<<256, 256>>>(proj_w, score_w1);                  // 0
    gemm_kernel<256, true><<<dim3(4, 352), 256>>>(x, nullptr);    // 1
    gram_kernel<<<dim3(NT, NT, 64), 256>>>();                     // 2
    select_kernel<<<dim3(BN/4, 4), 128>>>();                      // 3
    gemm_kernel<128, false><<<dim3(2, 352), 256>>>(x, score_b1);  // 4
    reduce_kernel<<<4, 256>>>();                                  // 5
    score_kernel<<<BN, 128>>>(score_w2, score_b2);                // 6
    gate_kernel<<<BN / 8, 256>>>(x, gate_w, gate_b);              // 7
    combine_kernel<<<dim3(NN, BATCH), 352>>>(out, tmask, smask, thr); // 8
}

// round 11
// speedup vs baseline: 2.6868x; 2.6868x over previous
#include <cuda_runtime.h>
#include <cstdint>

#define BATCH 16
#define NN 1408
#define DIM 256
#define HD 64
#define BN (BATCH*NN)
#define KSEL 211
#define NT 22
#define NPB (NT*NT*BATCH*4)
#define SZ ((size_t)BATCH*NN*NN)

typedef unsigned long long u64;

__device__ __align__(16) float g_z[(size_t)BN*DIM];
__device__ __align__(16) float g_h1[(size_t)BN*128];
__device__ __align__(16) float g_sq[4*BN];
__device__ __align__(16) float g_dist4[4*SZ];
__device__ __align__(16) float g_thr4[4*BN];
__device__ __align__(16) int   g_tie4[4*BN];
__device__ __align__(16) float g_score[BN];
__device__ __align__(16) float g_w[3*BN];
__device__ __align__(16) float g_projT[DIM*DIM];
__device__ __align__(16) float g_w1T[DIM*128];
__device__ __align__(16) float g_partial[NPB];
__device__ float g_inv4[4];

__device__ __forceinline__ u64 pack2(float lo, float hi){
    u64 r; asm("mov.b64 %0, {%1, %2};" : "=l"(r) : "f"(lo), "f"(hi)); return r;
}
__device__ __forceinline__ u64 fma2(u64 a, u64 b, u64 c){
    u64 d; asm("fma.rn.f32x2 %0, %1, %2, %3;" : "=l"(d) : "l"(a), "l"(b), "l"(c)); return d;
}
__device__ __forceinline__ float2 unpack2(u64 v){
    float2 f; asm("mov.b64 {%0, %1}, %2;" : "=f"(f.x), "=f"(f.y) : "l"(v)); return f;
}

__global__ void prep_kernel(const float* __restrict__ proj_w,
                            const float* __restrict__ score_w1) {
    int idx = blockIdx.x * 256 + threadIdx.x;
    int c = idx >> 8, k = idx & 255;
    g_projT[k * DIM + c] = proj_w[idx];
    if (idx < 128 * 256) g_w1T[k * 128 + c] = score_w1[idx];
}

template<int NOUT, bool IS_Z>
__global__ void __launch_bounds__(256, 4) gemm_kernel(const float* __restrict__ A,
                                                      const float* __restrict__ bias) {
    const float* Bt = IS_Z ? g_projT : g_w1T;
    float*       C  = IS_Z ? g_z     : g_h1;
    __shared__ __align__(16) float As[32][68];
    __shared__ __align__(16) float Bs[32][68];
    const int t = threadIdx.x, tx = t & 15, ty = t >> 4;
    const int m0 = blockIdx.y * 64, n0 = blockIdx.x * 64;
    u64 acc[4][2] = {};
    for (int k0 = 0; k0 < DIM; k0 += 32) {
        #pragma unroll
        for (int i = 0; i < 8; i++) {
            int e = t + i * 256, r = e >> 5, k = e & 31;
            As[k][r] = A[(size_t)(m0 + r) * DIM + k0 + k];
        }
        #pragma unroll
        for (int i = 0; i < 8; i++) {
            int e = t + i * 256, c = e & 63, k = e >> 6;
            Bs[k][c] = Bt[(size_t)(k0 + k) * NOUT + n0 + c];
        }
        __syncthreads();
        #pragma unroll 8
        for (int k = 0; k < 32; k++) {
            float4 bf = *reinterpret_cast<const float4*>(&Bs[k][tx*4]);
            float4 af = *reinterpret_cast<const float4*>(&As[k][ty*4]);
            u64 b01 = pack2(bf.x, bf.y), b23 = pack2(bf.z, bf.w);
            const float av[4] = {af.x, af.y, af.z, af.w};
            #pragma unroll
            for (int i = 0; i < 4; i++) {
                u64 aa = pack2(av[i], av[i]);
                acc[i][0] = fma2(aa, b01, acc[i][0]);
                acc[i][1] = fma2(aa, b23, acc[i][1]);
            }
        }
        __syncthreads();
    }
    #pragma unroll
    for (int i = 0; i < 4; i++) {
        float2 v01 = unpack2(acc[i][0]), v23 = unpack2(acc[i][1]);
        float v[4] = {v01.x, v01.y, v23.x, v23.y};
        float4 o;
        #pragma unroll
        for (int j = 0; j < 4; j++) {
            float val = v[j];
            if (!IS_Z) {
                val += bias[n0 + tx*4 + j];
                val = 0.5f * val * (1.0f + erff(val * 0.70710678118654752f));
            }
            ((float*)&o)[j] = val;
        }
        *reinterpret_cast<float4*>(&C[(size_t)(m0 + ty*4 + i) * NOUT + n0 + tx*4]) = o;
        if (IS_Z) {
            float sq = v[0]*v[0] + v[1]*v[1] + v[2]*v[2] + v[3]*v[3];
            #pragma unroll
            for (int off = 8; off; off >>= 1)
                sq += __shfl_down_sync(0xffffffffu, sq, off, 16);
            if (tx == 0) g_sq[blockIdx.x * BN + m0 + ty*4 + i] = sq;
        }
    }
}

__global__ void score_kernel(const float* __restrict__ w2, const float* __restrict__ b2) {
    const int n = blockIdx.x, t = threadIdx.x;
    float s = g_h1[(size_t)n * 128 + t] * w2[t];
    #pragma unroll
    for (int off = 16; off; off >>= 1) s += __shfl_down_sync(0xffffffffu, s, off);
    __shared__ float sw[4];
    if ((t & 31) == 0) sw[t >> 5] = s;
    __syncthreads();
    if (t == 0) {
        float v = sw[0] + sw[1] + sw[2] + sw[3] + b2[0];
        g_score[n] = 1.0f / (1.0f + expf(-v));
    }
}

__global__ void gate_kernel(const float* __restrict__ x, const float* __restrict__ gw,
                            const float* __restrict__ gb) {
    const int lane = threadIdx.x & 31;
    const int n = blockIdx.x * 8 + (threadIdx.x >> 5);
    const float* xr = x + (size_t)n * DIM;
    float a0 = 0.f, a1 = 0.f, a2 = 0.f;
    for (int k = lane; k < DIM; k += 32) {
        float xv = xr[k];
        a0 += xv * gw[k]; a1 += xv * gw[DIM + k]; a2 += xv * gw[2*DIM + k];
    }
    #pragma unroll
    for (int off = 16; off; off >>= 1) {
        a0 += __shfl_down_sync(0xffffffffu, a0, off);
        a1 += __shfl_down_sync(0xffffffffu, a1, off);
        a2 += __shfl_down_sync(0xffffffffu, a2, off);
    }
    if (lane == 0) {
        float p0 = a0 + gb[0], p1 = a1 + gb[1], p2 = a2 + gb[2];
        float mx = fmaxf(p0, fmaxf(p1, p2));
        float e0 = expf(p0 - mx), e1 = expf(p1 - mx), e2 = expf(p2 - mx);
        float es = e0 + e1 + e2;
        float pr[3] = {e0/es, e1/es, e2/es};
        int pos[3];
        #pragma unroll
        for (int a = 0; a < 3; a++) {
            int c = 0;
            #pragma unroll
            for (int b = 0; b < 3; b++)
                c += ((pr[b] > pr[a]) || (pr[b] == pr[a] && b < a)) ? 1 : 0;
            pos[a] = c;
        }
        float sp[3];
        #pragma unroll
        for (int a = 0; a < 3; a++) sp[pos[a]] = pr[a];
        float c1 = sp[0] + sp[1];
        float c2 = c1 + sp[2];
        if (!((c1 - sp[1]) < 0.85f)) sp[1] = 0.f;
        if (!((c2 - sp[2]) < 0.85f)) sp[2] = 0.f;
        float w0 = sp[pos[0]], w1 = sp[pos[1]], w2v = sp[pos[2]];
        float scale = 1.0f / (w0 + w1 + w2v + 1e-8f);
        g_w[n]        = w0  * scale;
        g_w[BN + n]   = w1  * scale;
        g_w[2*BN + n] = w2v * scale;
    }
}

__global__ void __launch_bounds__(256, 4) gram_kernel() {
    const int tj = blockIdx.x, ti = blockIdx.y;
    const int z = blockIdx.z, h = z >> 4, b = z & 15;
    const int pidx = z * (NT*NT) + ti*NT + tj;
    if (tj < ti) { if (threadIdx.x == 0) g_partial[pidx] = 0.f; return; }
    __shared__ __align__(16) float Az[64][68];
    __shared__ __align__(16) float Bz[64][68];
    __shared__ float sred[8];
    const int t = threadIdx.x, tx = t & 15, ty = t >> 4;
    const int i0 = ti*64, j0 = tj*64;
    const float* zb = g_z + (size_t)b * NN * DIM + h * HD;
    #pragma unroll
    for (int i = 0; i < 16; i++) {
        int e = t + i * 256, k = e & 63, r = e >> 6;
        Az[k][r] = zb[(size_t)(i0 + r) * DIM + k];
        Bz[k][r] = zb[(size_t)(j0 + r) * DIM + k];
    }
    __syncthreads();
    u64 acc[4][2] = {};
    #pragma unroll 16
    for (int k = 0; k < 64; k++) {
        float4 bf = *reinterpret_cast<const float4*>(&Bz[k][tx*4]);
        float4 af = *reinterpret_cast<const float4*>(&Az[k][ty*4]);
        u64 b01 = pack2(bf.x, bf.y), b23 = pack2(bf.z, bf.w);
        const float av[4] = {af.x, af.y, af.z, af.w};
        #pragma unroll
        for (int i = 0; i < 4; i++) {
            u64 aa = pack2(av[i], av[i]);
            acc[i][0] = fma2(aa, b01, acc[i][0]);
            acc[i][1] = fma2(aa, b23, acc[i][1]);
        }
    }
    const float* sqb = g_sq + h * BN + b * NN;
    float* dbase = g_dist4 + (size_t)h * SZ + (size_t)b * NN * NN;
    float lsum = 0.f;
    float dval[4][4];
    #pragma unroll
    for (int i = 0; i < 4; i++) {
        float sqi = sqb[i0 + ty*4 + i];
        float2 v01 = unpack2(acc[i][0]), v23 = unpack2(acc[i][1]);
        float dot[4] = {v01.x, v01.y, v23.x, v23.y};
        #pragma unroll
        for (int j = 0; j < 4; j++) {
            float d2 = sqi + sqb[j0 + tx*4 + j] - 2.0f * dot[j];
            float dv = (d2 > 0.f) ? sqrtf(d2) : 0.f;
            dval[i][j] = dv;
            lsum += dv;
        }
        *reinterpret_cast<float4*>(&dbase[(size_t)(i0 + ty*4 + i) * NN + j0 + tx*4]) =
            make_float4(dval[i][0], dval[i][1], dval[i][2], dval[i][3]);
    }
    #pragma unroll
    for (int off = 16; off; off >>= 1) lsum += __shfl_down_sync(0xffffffffu, lsum, off);
    if ((t & 31) == 0) sred[t >> 5] = lsum;
    if (tj > ti) {
        __syncthreads();
        #pragma unroll
        for (int i = 0; i < 4; i++)
            #pragma unroll
            for (int j = 0; j < 4; j++)
                Az[tx*4 + j][ty*4 + i] = dval[i][j];
        __syncthreads();
        #pragma unroll
        for (int it = 0; it < 16; it++) {
            int e = t + it * 256, c = e & 63, r = e >> 6;
            dbase[(size_t)(j0 + r) * NN + i0 + c] = Az[r][c];
        }
    } else {
        __syncthreads();
    }
    if (t == 0) {
        float s = 0.f;
        #pragma unroll
        for (int wv = 0; wv < 8; wv++) s += sred[wv];
        g_partial[pidx] = (tj > ti) ? 2.0f * s : s;
    }
}

__global__ void reduce_kernel() {
    const int h = blockIdx.x;
    __shared__ float s[256];
    float a = 0.f;
    for (int i = threadIdx.x; i < NT*NT*BATCH; i += 256)
        a += g_partial[h * (NT*NT*BATCH) + i];
    s[threadIdx.x] = a;
    __syncthreads();
    for (int off = 128; off; off >>= 1) {
        if (threadIdx.x < off) s[threadIdx.x] += s[threadIdx.x + off];
        __syncthreads();
    }
    if (threadIdx.x == 0) {
        float mean = s[0] / 31719424.0f;
        g_inv4[h] = 1.0f / (2.0f * mean * mean + 1e-8f);
    }
}

// proven hist8 radix select (R8: 423us @ issue 78.5%)
__global__ void select_kernel() {
    __shared__ unsigned rowv[NN];
    __shared__ unsigned hist8[8][256];
    __shared__ unsigned wsum[8];
    __shared__ int sh[4];
    const int t = threadIdx.x, w = t >> 5, lane = t & 31;
    const int row = blockIdx.x;
    const int h = 3 - blockIdx.y;      // head 3 first: last written by gram -> L2 hits
    const float* dp = g_dist4 + (size_t)h * SZ + (size_t)row * NN;
    unsigned myv[6];
    #pragma unroll
    for (int i = 0; i < 6; i++) {
        int j = t + i * 256;
        unsigned u = (j < NN) ? __float_as_uint(dp[j]) : 0xFFFFFFFFu;
        myv[i] = u;
        if (j < NN) rowv[j] = u;
    }
    __syncthreads();
    unsigned prefix = 0; int rem = KSEL, ceq = 0;
    #pragma unroll
    for (int pass = 0; pass < 4; pass++) {
        const int shift = 24 - 8 * pass;
        const unsigned himask = pass ? (0xFFFFFFFFu << (shift + 8)) : 0u;
        for (int i = t; i < 2048; i += 256) ((unsigned*)hist8)[i] = 0;
        __syncthreads();
        #pragma unroll
        for (int i = 0; i < 6; i++) {
            unsigned u = myv[i];
            if (((u & himask) == prefix) && (t + i * 256 < NN))
                atomicAdd(&hist8[w][(u >> shift) & 255u], 1u);
        }
        __syncthreads();
        unsigned v = 0;
        #pragma unroll
        for (int i = 0; i < 8; i++) v += hist8[i][t];
        unsigned incl = v;
        #pragma unroll
        for (int o = 1; o < 32; o <<= 1) {
            unsigned nb = __shfl_up_sync(0xffffffffu, incl, o);
            if (lane >= o) incl += nb;
        }
        if (lane == 31) wsum[w] = incl;
        __syncthreads();
        unsigned wo = 0;
        #pragma unroll
        for (int i = 0; i < 8; i++) if (i < w) wo += wsum[i];
        incl += wo;
        unsigned excl = incl - v;
        if (excl < (unsigned)rem && (unsigned)rem <= incl) {
            sh[0] = t; sh[1] = rem - (int)excl; sh[2] = (int)v;
        }
        __syncthreads();
        prefix |= ((unsigned)sh[0]) << shift;
        rem = sh[1]; ceq = sh[2];
        __syncthreads();
    }
    int tieIdx;
    if (rem >= ceq) {
        tieIdx = 0x7fffffff;
    } else {
        if (t == 0) {
            int c = 0, tiv = NN;
            for (int j = 0; j < NN; j++)
                if (rowv[j] == prefix) { if (++c == rem) { tiv = j; break; } }
            sh[3] = tiv;
        }
        __syncthreads();
        tieIdx = sh[3];
    }
    if (t == 0) { g_thr4[h*BN + row] = __uint_as_float(prefix); g_tie4[h*BN + row] = tieIdx; }
}

__global__ void combine_kernel(float* __restrict__ out,
                               const float* __restrict__ tmask,
                               const float* __restrict__ smask,
                               const float* __restrict__ thrp) {
    const int i = blockIdx.x, b = blockIdx.y;
    const int row = b * NN + i;
    const int j0 = threadIdx.x * 4;
    const size_t roff = (size_t)b * NN * NN + (size_t)i * NN + j0;
    float adj[4] = {0.f, 0.f, 0.f, 0.f};
    #pragma unroll
    for (int h = 0; h < 4; h++) {
        const float inv  = g_inv4[h];
        const float thri = g_thr4[h*BN + row];
        const int   tiei = g_tie4[h*BN + row];
        const float4 d4  = *reinterpret_cast<const float4*>(&g_dist4[(size_t)h * SZ + roff]);
        const float4 tj4 = *reinterpret_cast<const float4*>(&g_thr4[h*BN + b*NN + j0]);
        const int4   te4 = *reinterpret_cast<const int4*>(&g_tie4[h*BN + b*NN + j0]);
        const float dv[4]  = {d4.x, d4.y, d4.z, d4.w};
        const float tjv[4] = {tj4.x, tj4.y, tj4.z, tj4.w};
        const int   tev[4] = {te4.x, te4.y, te4.z, te4.w};
        #pragma unroll
        for (int l = 0; l < 4; l++) {
            int j = j0 + l;
            float d = dv[l];
            bool m = (d < thri) || (d == thri && j <= tiei) ||
                     (d < tjv[l]) || (d == tjv[l] && i <= tev[l]);
            if (m) adj[l] += __expf(-d * d * inv);
        }
    }
    const float T   = thrp[0];
    const float si  = g_score[row];
    const float wti = g_w[row], wsi = g_w[BN + row], wpi = g_w[2*BN + row];
    const float4 sj  = *reinterpret_cast<const float4*>(&g_score[b*NN + j0]);
    const float4 wtj = *reinterpret_cast<const float4*>(&g_w[b*NN + j0]);
    const float4 wsj = *reinterpret_cast<const float4*>(&g_w[BN + b*NN + j0]);
    const float4 wpj = *reinterpret_cast<const float4*>(&g_w[2*BN + b*NN + j0]);
    const float4 tm4 = *reinterpret_cast<const float4*>(&tmask[(size_t)i * NN + j0]);
    const float4 sm4 = *reinterpret_cast<const float4*>(&smask[(size_t)i * NN + j0]);
    const float sjv[4]  = {sj.x, sj.y, sj.z, sj.w};
    const float wtjv[4] = {wtj.x, wtj.y, wtj.z, wtj.w};
    const float wsjv[4] = {wsj.x, wsj.y, wsj.z, wsj.w};
    const float wpjv[4] = {wpj.x, wpj.y, wpj.z, wpj.w};
    const float tmv[4]  = {tm4.x, tm4.y, tm4.z, tm4.w};
    const float smv[4]  = {sm4.x, sm4.y, sm4.z, sm4.w};
    float4 res;
    #pragma unroll
    for (int l = 0; l < 4; l++) {
        float a = adj[l] * 0.25f;
        float gate_t = tmv[l] * 0.5f * (wti + wtjv[l]);
        float gate_s = smv[l] * 0.5f * (wsi + wsjv[l]);
        float ew  = si * sjv[l];
        // sigmoid(10(ew-T)) = 1/(1+2^(K(T-ew))), reciprocal via Newton (no RCP slow path)
        float e2  = exp2f(14.4269504088896341f * (T - ew));
        float den = 1.0f + e2;
        float r = __uint_as_float(0x7EF311C3u - __float_as_uint(den));
        r = r * (2.0f - den * r);
        r = r * (2.0f - den * r);
        r = r * (2.0f - den * r);
        float gate_p = r * 0.5f * (wpi + wpjv[l]);
        ((float*)&res)[l] = a * (gate_t + gate_s + gate_p);
    }
    *reinterpret_cast<float4*>(&out[roff]) = res;
}

extern "C" void kernel_launch(void* const* d_in, const int* in_sizes, int n_in,
                              void* d_out, int out_size) {
    const float* x        = (const float*)d_in[0];
    const float* proj_w   = (const float*)d_in[1];
    const float* gate_w   = (const float*)d_in[2];
    const float* gate_b   = (const float*)d_in[3];
    const float* score_w1 = (const float*)d_in[4];
    const float* score_b1 = (const float*)d_in[5];
    const float* score_w2 = (const float*)d_in[6];
    const float* score_b2 = (const float*)d_in[7];
    const float* thr      = (const float*)d_in[8];
    const float* tmask    = (const float*)d_in[9];
    const float* smask    = (const float*)d_in[10];
    float* out = (float*)d_out;

    // capture slot #3 = hist8 select (silicon-speed canary: 423us baseline)
    prep_kernel<<<256, 256>>>(proj_w, score_w1);                  // 0
    gemm_kernel<256, true><<<dim3(4, 352), 256>>>(x, nullptr);    // 1
    gram_kernel<<<dim3(NT, NT, 64), 256>>>();                     // 2
    select_kernel<<<dim3(BN, 4), 256>>>();                        // 3
    gemm_kernel<128, false><<<dim3(2, 352), 256>>>(x, score_b1);  // 4
    reduce_kernel<<<4, 256>>>();                                  // 5
    score_kernel<<<BN, 128>>>(score_w2, score_b2);                // 6
    gate_kernel<<<BN / 8, 256>>>(x, gate_w, gate_b);              // 7
    combine_kernel<<<dim3(NN, BATCH), 352>>>(out, tmask, smask, thr); // 8
}

// round 12
// speedup vs baseline: 2.7177x; 1.0115x over previous
#include <cuda_runtime.h>
#include <cstdint>

#define BATCH 16
#define NN 1408
#define DIM 256
#define HD 64
#define BN (BATCH*NN)
#define KSEL 211
#define NT 22
#define NPB (NT*NT*BATCH*4)
#define SZ ((size_t)BATCH*NN*NN)

typedef unsigned long long u64;

__device__ __align__(16) float g_z[(size_t)BN*DIM];
__device__ __align__(16) float g_h1[(size_t)BN*128];
__device__ __align__(16) float g_sq[4*BN];
__device__ __align__(16) float g_dist4[4*SZ];
__device__ __align__(16) float g_thr4[4*BN];
__device__ __align__(16) int   g_tie4[4*BN];
__device__ __align__(16) float g_score[BN];
__device__ __align__(16) float g_w[3*BN];
__device__ __align__(16) float g_projT[DIM*DIM];
__device__ __align__(16) float g_w1T[DIM*128];
__device__ __align__(16) float g_partial[NPB];
__device__ float g_inv4[4];

__device__ __forceinline__ u64 pack2(float lo, float hi){
    u64 r; asm("mov.b64 %0, {%1, %2};" : "=l"(r) : "f"(lo), "f"(hi)); return r;
}
__device__ __forceinline__ u64 fma2(u64 a, u64 b, u64 c){
    u64 d; asm("fma.rn.f32x2 %0, %1, %2, %3;" : "=l"(d) : "l"(a), "l"(b), "l"(c)); return d;
}
__device__ __forceinline__ float2 unpack2(u64 v){
    float2 f; asm("mov.b64 {%0, %1}, %2;" : "=f"(f.x), "=f"(f.y) : "l"(v)); return f;
}

__global__ void prep_kernel(const float* __restrict__ proj_w,
                            const float* __restrict__ score_w1) {
    int idx = blockIdx.x * 256 + threadIdx.x;
    int c = idx >> 8, k = idx & 255;
    g_projT[k * DIM + c] = proj_w[idx];
    if (idx < 128 * 256) g_w1T[k * 128 + c] = score_w1[idx];
}

template<int NOUT, bool IS_Z>
__global__ void __launch_bounds__(256, 4) gemm_kernel(const float* __restrict__ A,
                                                      const float* __restrict__ bias) {
    const float* Bt = IS_Z ? g_projT : g_w1T;
    float*       C  = IS_Z ? g_z     : g_h1;
    __shared__ __align__(16) float As[32][68];
    __shared__ __align__(16) float Bs[32][68];
    const int t = threadIdx.x, tx = t & 15, ty = t >> 4;
    const int m0 = blockIdx.y * 64, n0 = blockIdx.x * 64;
    u64 acc[4][2] = {};
    for (int k0 = 0; k0 < DIM; k0 += 32) {
        #pragma unroll
        for (int i = 0; i < 8; i++) {
            int e = t + i * 256, r = e >> 5, k = e & 31;
            As[k][r] = A[(size_t)(m0 + r) * DIM + k0 + k];
        }
        #pragma unroll
        for (int i = 0; i < 8; i++) {
            int e = t + i * 256, c = e & 63, k = e >> 6;
            Bs[k][c] = Bt[(size_t)(k0 + k) * NOUT + n0 + c];
        }
        __syncthreads();
        #pragma unroll 8
        for (int k = 0; k < 32; k++) {
            float4 bf = *reinterpret_cast<const float4*>(&Bs[k][tx*4]);
            float4 af = *reinterpret_cast<const float4*>(&As[k][ty*4]);
            u64 b01 = pack2(bf.x, bf.y), b23 = pack2(bf.z, bf.w);
            const float av[4] = {af.x, af.y, af.z, af.w};
            #pragma unroll
            for (int i = 0; i < 4; i++) {
                u64 aa = pack2(av[i], av[i]);
                acc[i][0] = fma2(aa, b01, acc[i][0]);
                acc[i][1] = fma2(aa, b23, acc[i][1]);
            }
        }
        __syncthreads();
    }
    #pragma unroll
    for (int i = 0; i < 4; i++) {
        float2 v01 = unpack2(acc[i][0]), v23 = unpack2(acc[i][1]);
        float v[4] = {v01.x, v01.y, v23.x, v23.y};
        float4 o;
        #pragma unroll
        for (int j = 0; j < 4; j++) {
            float val = v[j];
            if (!IS_Z) {
                val += bias[n0 + tx*4 + j];
                val = 0.5f * val * (1.0f + erff(val * 0.70710678118654752f));
            }
            ((float*)&o)[j] = val;
        }
        *reinterpret_cast<float4*>(&C[(size_t)(m0 + ty*4 + i) * NOUT + n0 + tx*4]) = o;
        if (IS_Z) {
            float sq = v[0]*v[0] + v[1]*v[1] + v[2]*v[2] + v[3]*v[3];
            #pragma unroll
            for (int off = 8; off; off >>= 1)
                sq += __shfl_down_sync(0xffffffffu, sq, off, 16);
            if (tx == 0) g_sq[blockIdx.x * BN + m0 + ty*4 + i] = sq;
        }
    }
}

__global__ void score_kernel(const float* __restrict__ w2, const float* __restrict__ b2) {
    const int n = blockIdx.x, t = threadIdx.x;
    float s = g_h1[(size_t)n * 128 + t] * w2[t];
    #pragma unroll
    for (int off = 16; off; off >>= 1) s += __shfl_down_sync(0xffffffffu, s, off);
    __shared__ float sw[4];
    if ((t & 31) == 0) sw[t >> 5] = s;
    __syncthreads();
    if (t == 0) {
        float v = sw[0] + sw[1] + sw[2] + sw[3] + b2[0];
        g_score[n] = 1.0f / (1.0f + expf(-v));
    }
}

__global__ void gate_kernel(const float* __restrict__ x, const float* __restrict__ gw,
                            const float* __restrict__ gb) {
    const int lane = threadIdx.x & 31;
    const int n = blockIdx.x * 8 + (threadIdx.x >> 5);
    const float* xr = x + (size_t)n * DIM;
    float a0 = 0.f, a1 = 0.f, a2 = 0.f;
    for (int k = lane; k < DIM; k += 32) {
        float xv = xr[k];
        a0 += xv * gw[k]; a1 += xv * gw[DIM + k]; a2 += xv * gw[2*DIM + k];
    }
    #pragma unroll
    for (int off = 16; off; off >>= 1) {
        a0 += __shfl_down_sync(0xffffffffu, a0, off);
        a1 += __shfl_down_sync(0xffffffffu, a1, off);
        a2 += __shfl_down_sync(0xffffffffu, a2, off);
    }
    if (lane == 0) {
        float p0 = a0 + gb[0], p1 = a1 + gb[1], p2 = a2 + gb[2];
        float mx = fmaxf(p0, fmaxf(p1, p2));
        float e0 = expf(p0 - mx), e1 = expf(p1 - mx), e2 = expf(p2 - mx);
        float es = e0 + e1 + e2;
        float pr[3] = {e0/es, e1/es, e2/es};
        int pos[3];
        #pragma unroll
        for (int a = 0; a < 3; a++) {
            int c = 0;
            #pragma unroll
            for (int b = 0; b < 3; b++)
                c += ((pr[b] > pr[a]) || (pr[b] == pr[a] && b < a)) ? 1 : 0;
            pos[a] = c;
        }
        float sp[3];
        #pragma unroll
        for (int a = 0; a < 3; a++) sp[pos[a]] = pr[a];
        float c1 = sp[0] + sp[1];
        float c2 = c1 + sp[2];
        if (!((c1 - sp[1]) < 0.85f)) sp[1] = 0.f;
        if (!((c2 - sp[2]) < 0.85f)) sp[2] = 0.f;
        float w0 = sp[pos[0]], w1 = sp[pos[1]], w2v = sp[pos[2]];
        float scale = 1.0f / (w0 + w1 + w2v + 1e-8f);
        g_w[n]        = w0  * scale;
        g_w[BN + n]   = w1  * scale;
        g_w[2*BN + n] = w2v * scale;
    }
}

__global__ void __launch_bounds__(256, 4) gram_kernel() {
    const int tj = blockIdx.x, ti = blockIdx.y;
    const int z = blockIdx.z, h = z >> 4, b = z & 15;
    const int pidx = z * (NT*NT) + ti*NT + tj;
    if (tj < ti) { if (threadIdx.x == 0) g_partial[pidx] = 0.f; return; }
    __shared__ __align__(16) float Az[64][68];
    __shared__ __align__(16) float Bz[64][68];
    __shared__ float sred[8];
    const int t = threadIdx.x, tx = t & 15, ty = t >> 4;
    const int i0 = ti*64, j0 = tj*64;
    const float* zb = g_z + (size_t)b * NN * DIM + h * HD;
    #pragma unroll
    for (int i = 0; i < 16; i++) {
        int e = t + i * 256, k = e & 63, r = e >> 6;
        Az[k][r] = zb[(size_t)(i0 + r) * DIM + k];
        Bz[k][r] = zb[(size_t)(j0 + r) * DIM + k];
    }
    __syncthreads();
    u64 acc[4][2] = {};
    #pragma unroll 16
    for (int k = 0; k < 64; k++) {
        float4 bf = *reinterpret_cast<const float4*>(&Bz[k][tx*4]);
        float4 af = *reinterpret_cast<const float4*>(&Az[k][ty*4]);
        u64 b01 = pack2(bf.x, bf.y), b23 = pack2(bf.z, bf.w);
        const float av[4] = {af.x, af.y, af.z, af.w};
        #pragma unroll
        for (int i = 0; i < 4; i++) {
            u64 aa = pack2(av[i], av[i]);
            acc[i][0] = fma2(aa, b01, acc[i][0]);
            acc[i][1] = fma2(aa, b23, acc[i][1]);
        }
    }
    const float* sqb = g_sq + h * BN + b * NN;
    float* dbase = g_dist4 + (size_t)h * SZ + (size_t)b * NN * NN;
    float lsum = 0.f;
    float dval[4][4];
    #pragma unroll
    for (int i = 0; i < 4; i++) {
        float sqi = sqb[i0 + ty*4 + i];
        float2 v01 = unpack2(acc[i][0]), v23 = unpack2(acc[i][1]);
        float dot[4] = {v01.x, v01.y, v23.x, v23.y};
        #pragma unroll
        for (int j = 0; j < 4; j++) {
            float d2 = sqi + sqb[j0 + tx*4 + j] - 2.0f * dot[j];
            float dv = (d2 > 0.f) ? sqrtf(d2) : 0.f;
            dval[i][j] = dv;
            lsum += dv;
        }
        *reinterpret_cast<float4*>(&dbase[(size_t)(i0 + ty*4 + i) * NN + j0 + tx*4]) =
            make_float4(dval[i][0], dval[i][1], dval[i][2], dval[i][3]);
    }
    #pragma unroll
    for (int off = 16; off; off >>= 1) lsum += __shfl_down_sync(0xffffffffu, lsum, off);
    if ((t & 31) == 0) sred[t >> 5] = lsum;
    if (tj > ti) {
        __syncthreads();
        #pragma unroll
        for (int i = 0; i < 4; i++)
            #pragma unroll
            for (int j = 0; j < 4; j++)
                Az[tx*4 + j][ty*4 + i] = dval[i][j];
        __syncthreads();
        #pragma unroll
        for (int it = 0; it < 16; it++) {
            int e = t + it * 256, c = e & 63, r = e >> 6;
            dbase[(size_t)(j0 + r) * NN + i0 + c] = Az[r][c];
        }
    } else {
        __syncthreads();
    }
    if (t == 0) {
        float s = 0.f;
        #pragma unroll
        for (int wv = 0; wv < 8; wv++) s += sred[wv];
        g_partial[pidx] = (tj > ti) ? 2.0f * s : s;
    }
}

__global__ void reduce_kernel() {
    const int h = blockIdx.x;
    __shared__ float s[256];
    float a = 0.f;
    for (int i = threadIdx.x; i < NT*NT*BATCH; i += 256)
        a += g_partial[h * (NT*NT*BATCH) + i];
    s[threadIdx.x] = a;
    __syncthreads();
    for (int off = 128; off; off >>= 1) {
        if (threadIdx.x < off) s[threadIdx.x] += s[threadIdx.x + off];
        __syncthreads();
    }
    if (threadIdx.x == 0) {
        float mean = s[0] / 31719424.0f;
        g_inv4[h] = 1.0f / (2.0f * mean * mean + 1e-8f);
    }
}

// hist8 radix select v2: zero-once + rezero-touched, register bin-find,
// 3 syncthreads/pass (was 4). Results bit-identical to v1 (R8/R10).
__global__ void select_kernel() {
    __shared__ unsigned rowv[NN];
    __shared__ unsigned hist8[8][256];
    __shared__ unsigned wsum[8];
    __shared__ int sh[4];
    const int t = threadIdx.x, w = t >> 5, lane = t & 31;
    const int row = blockIdx.x;
    const int h = 3 - blockIdx.y;      // head 3 first: last written by gram -> L2 hits
    const float* dp = g_dist4 + (size_t)h * SZ + (size_t)row * NN;
    unsigned myv[6];
    #pragma unroll
    for (int i = 0; i < 6; i++) {
        int j = t + i * 256;
        unsigned u = (j < NN) ? __float_as_uint(dp[j]) : 0xFFFFFFFFu;
        myv[i] = u;
        if (j < NN) rowv[j] = u;
    }
    #pragma unroll
    for (int i = 0; i < 8; i++) hist8[i][t] = 0;   // zero ONCE
    __syncthreads();
    unsigned prefix = 0; int rem = KSEL, ceq = 0;
    #pragma unroll
    for (int pass = 0; pass < 4; pass++) {
        const int shift = 24 - 8 * pass;
        const unsigned himask = pass ? (0xFFFFFFFFu << (shift + 8)) : 0u;
        #pragma unroll
        for (int i = 0; i < 6; i++) {
            unsigned u = myv[i];
            if (((u & himask) == prefix) && (t + i * 256 < NN))
                atomicAdd(&hist8[w][(u >> shift) & 255u], 1u);
        }
        __syncthreads();                            // A: atomics visible
        unsigned hv[8], v = 0;
        #pragma unroll
        for (int i = 0; i < 8; i++) { hv[i] = hist8[i][t]; v += hv[i]; }
        if (v) {                                    // rezero only touched (thread-private slots)
            #pragma unroll
            for (int i = 0; i < 8; i++) if (hv[i]) hist8[i][t] = 0;
        }
        unsigned incl = v;
        #pragma unroll
        for (int o = 1; o < 32; o <<= 1) {
            unsigned nb = __shfl_up_sync(0xffffffffu, incl, o);
            if (lane >= o) incl += nb;
        }
        if (lane == 31) wsum[w] = incl;
        __syncthreads();                            // B: wsum + rezero visible
        unsigned wo = 0;
        #pragma unroll
        for (int i = 0; i < 8; i++) if (i < w) wo += wsum[i];
        incl += wo;
        unsigned excl = incl - v;
        if (excl < (unsigned)rem && (unsigned)rem <= incl) {
            sh[0] = t; sh[1] = rem - (int)excl; sh[2] = (int)v;
        }
        __syncthreads();                            // C: sh visible
        prefix |= ((unsigned)sh[0]) << shift;
        rem = sh[1]; ceq = sh[2];
    }
    int tieIdx;
    if (rem >= ceq) {
        tieIdx = 0x7fffffff;
    } else {
        if (t == 0) {
            int c = 0, tiv = NN;
            for (int j = 0; j < NN; j++)
                if (rowv[j] == prefix) { if (++c == rem) { tiv = j; break; } }
            sh[3] = tiv;
        }
        __syncthreads();
        tieIdx = sh[3];
    }
    if (t == 0) { g_thr4[h*BN + row] = __uint_as_float(prefix); g_tie4[h*BN + row] = tieIdx; }
}

__global__ void combine_kernel(float* __restrict__ out,
                               const float* __restrict__ tmask,
                               const float* __restrict__ smask,
                               const float* __restrict__ thrp) {
    const int i = blockIdx.x, b = blockIdx.y;
    const int row = b * NN + i;
    const int j0 = threadIdx.x * 4;
    const size_t roff = (size_t)b * NN * NN + (size_t)i * NN + j0;
    float adj[4] = {0.f, 0.f, 0.f, 0.f};
    #pragma unroll
    for (int h = 0; h < 4; h++) {
        const float inv  = g_inv4[h];
        const float thri = g_thr4[h*BN + row];
        const int   tiei = g_tie4[h*BN + row];
        const float4 d4  = *reinterpret_cast<const float4*>(&g_dist4[(size_t)h * SZ + roff]);
        const float4 tj4 = *reinterpret_cast<const float4*>(&g_thr4[h*BN + b*NN + j0]);
        const int4   te4 = *reinterpret_cast<const int4*>(&g_tie4[h*BN + b*NN + j0]);
        const float dv[4]  = {d4.x, d4.y, d4.z, d4.w};
        const float tjv[4] = {tj4.x, tj4.y, tj4.z, tj4.w};
        const int   tev[4] = {te4.x, te4.y, te4.z, te4.w};
        #pragma unroll
        for (int l = 0; l < 4; l++) {
            int j = j0 + l;
            float d = dv[l];
            bool m = (d < thri) || (d == thri && j <= tiei) ||
                     (d < tjv[l]) || (d == tjv[l] && i <= tev[l]);
            if (m) adj[l] += __expf(-d * d * inv);
        }
    }
    const float T   = thrp[0];
    const float si  = g_score[row];
    const float wti = g_w[row], wsi = g_w[BN + row], wpi = g_w[2*BN + row];
    const float4 sj  = *reinterpret_cast<const float4*>(&g_score[b*NN + j0]);
    const float4 wtj = *reinterpret_cast<const float4*>(&g_w[b*NN + j0]);
    const float4 wsj = *reinterpret_cast<const float4*>(&g_w[BN + b*NN + j0]);
    const float4 wpj = *reinterpret_cast<const float4*>(&g_w[2*BN + b*NN + j0]);
    const float4 tm4 = *reinterpret_cast<const float4*>(&tmask[(size_t)i * NN + j0]);
    const float4 sm4 = *reinterpret_cast<const float4*>(&smask[(size_t)i * NN + j0]);
    const float sjv[4]  = {sj.x, sj.y, sj.z, sj.w};
    const float wtjv[4] = {wtj.x, wtj.y, wtj.z, wtj.w};
    const float wsjv[4] = {wsj.x, wsj.y, wsj.z, wsj.w};
    const float wpjv[4] = {wpj.x, wpj.y, wpj.z, wpj.w};
    const float tmv[4]  = {tm4.x, tm4.y, tm4.z, tm4.w};
    const float smv[4]  = {sm4.x, sm4.y, sm4.z, sm4.w};
    float4 res;
    #pragma unroll
    for (int l = 0; l < 4; l++) {
        float a = adj[l] * 0.25f;
        float gate_t = tmv[l] * 0.5f * (wti + wtjv[l]);
        float gate_s = smv[l] * 0.5f * (wsi + wsjv[l]);
        float ew  = si * sjv[l];
        float e2  = exp2f(14.4269504088896341f * (T - ew));
        float den = 1.0f + e2;
        float r = __uint_as_float(0x7EF311C3u - __float_as_uint(den));
        r = r * (2.0f - den * r);
        r = r * (2.0f - den * r);
        r = r * (2.0f - den * r);
        float gate_p = r * 0.5f * (wpi + wpjv[l]);
        ((float*)&res)[l] = a * (gate_t + gate_s + gate_p);
    }
    *reinterpret_cast<float4*>(&out[roff]) = res;
}

extern "C" void kernel_launch(void* const* d_in, const int* in_sizes, int n_in,
                              void* d_out, int out_size) {
    const float* x        = (const float*)d_in[0];
    const float* proj_w   = (const float*)d_in[1];
    const float* gate_w   = (const float*)d_in[2];
    const float* gate_b   = (const float*)d_in[3];
    const float* score_w1 = (const float*)d_in[4];
    const float* score_b1 = (const float*)d_in[5];
    const float* score_w2 = (const float*)d_in[6];
    const float* score_b2 = (const float*)d_in[7];
    const float* thr      = (const float*)d_in[8];
    const float* tmask    = (const float*)d_in[9];
    const float* smask    = (const float*)d_in[10];
    float* out = (float*)d_out;

    // capture slot #3 = select v2 (direct verification vs 423us baseline)
    prep_kernel<<<256, 256>>>(proj_w, score_w1);                  // 0
    gemm_kernel<256, true><<<dim3(4, 352), 256>>>(x, nullptr);    // 1
    gram_kernel<<<dim3(NT, NT, 64), 256>>>();                     // 2
    select_kernel<<<dim3(BN, 4), 256>>>();                        // 3
    gemm_kernel<128, false><<<dim3(2, 352), 256>>>(x, score_b1);  // 4
    reduce_kernel<<<4, 256>>>();                                  // 5
    score_kernel<<<BN, 128>>>(score_w2, score_b2);                // 6
    gate_kernel<<<BN / 8, 256>>>(x, gate_w, gate_b);              // 7
    combine_kernel<<<dim3(NN, BATCH), 352>>>(out, tmask, smask, thr); // 8
}